// round 15
// baseline (speedup 1.0000x reference)
#include <cuda_runtime.h>
#include <cuda_bf16.h>
#include <math.h>
#include <stdint.h>

// Problem shape (fixed)
#define B_  32
#define Ls  512
#define D_  768
#define Kp  8192
#define M_  (B_ * Ls)        // 16384

// ---------------- device scratch (allocation-free) -------------------------
__device__ float g_logits[(size_t)M_ * Kp];           // fp32 logits (compact rows)
__device__ float g_c[M_];                             // per-row m + log(sum exp)
__device__ __nv_bfloat16 g_Qh[(size_t)M_ * D_];
__device__ __nv_bfloat16 g_Ql[(size_t)M_ * D_];
__device__ __nv_bfloat16 g_Ph[(size_t)Kp * D_];
__device__ __nv_bfloat16 g_Pl[(size_t)Kp * D_];
__device__ int g_off[B_ + 2];        // [0..32] offsets; [32]=valid; [33]=padded
__device__ int g_rowidx[M_];         // compact row -> original row

// ---------------- PTX helpers ------------------------------------------------
__device__ __forceinline__ uint32_t smem_u32(const void* p) {
    uint32_t a;
    asm("{ .reg .u64 t; cvta.to.shared.u64 t, %1; cvt.u32.u64 %0, t; }"
        : "=r"(a) : "l"(p));
    return a;
}
__device__ __forceinline__ void cp16(uint32_t dst, const void* src) {
    asm volatile("cp.async.cg.shared.global [%0], [%1], 16;" :: "r"(dst), "l"(src));
}
__device__ __forceinline__ void cp_commit() {
    asm volatile("cp.async.commit_group;" ::: "memory");
}
__device__ __forceinline__ void ldm_x4(uint32_t* r, uint32_t addr) {
    asm volatile("ldmatrix.sync.aligned.m8n8.x4.shared.b16 {%0,%1,%2,%3}, [%4];"
                 : "=r"(r[0]), "=r"(r[1]), "=r"(r[2]), "=r"(r[3]) : "r"(addr));
}
__device__ __forceinline__ void mma16816(float* c, const uint32_t* a, const uint32_t* b) {
    asm volatile(
        "mma.sync.aligned.m16n8k16.row.col.f32.bf16.bf16.f32 "
        "{%0,%1,%2,%3}, {%4,%5,%6,%7}, {%8,%9}, {%0,%1,%2,%3};"
        : "+f"(c[0]), "+f"(c[1]), "+f"(c[2]), "+f"(c[3])
        : "r"(a[0]), "r"(a[1]), "r"(a[2]), "r"(a[3]), "r"(b[0]), "r"(b[1]));
}

// ---------------- fused mask compaction (single CTA) -------------------------
// Phase 1: per-batch valid counts.  Phase 2: warp scan of counts -> offsets.
// Phase 3: re-ballot + scatter compact row indices.
__global__ __launch_bounds__(Ls)
void mask_all(const int* __restrict__ mask)
{
    const int tid = threadIdx.x;              // 0..511
    const int lane = tid & 31, w = tid >> 5;  // 16 warps
    __shared__ int ws[16];
    __shared__ int cntS[B_];
    __shared__ int offS[B_ + 1];

    // phase 1: counts per batch
    for (int b = 0; b < B_; b++) {
        int v = mask[b * Ls + tid] ? 1 : 0;
        unsigned bal = __ballot_sync(0xffffffffu, v);
        if (lane == 0) ws[w] = __popc(bal);
        __syncthreads();
        if (tid == 0) {
            int s = 0;
#pragma unroll
            for (int i = 0; i < 16; i++) s += ws[i];
            cntS[b] = s;
        }
        __syncthreads();
    }

    // phase 2: exclusive scan of 32 counts (warp 0)
    if (tid < 32) {
        int x = cntS[tid];
#pragma unroll
        for (int o = 1; o < 32; o <<= 1) {
            int y = __shfl_up_sync(0xffffffffu, x, o);
            if (tid >= o) x += y;
        }
        offS[tid + 1] = x;
        g_off[tid + 1] = x;
        if (tid == 0) { offS[0] = 0; g_off[0] = 0; }
        if (tid == 31) g_off[B_ + 1] = (x + 127) & ~127;   // padded (TILE_M=128)
    }
    __syncthreads();

    // phase 3: scatter
    for (int b = 0; b < B_; b++) {
        int v = mask[b * Ls + tid] ? 1 : 0;
        unsigned bal = __ballot_sync(0xffffffffu, v);
        int pre = __popc(bal & ((1u << lane) - 1u));
        if (lane == 0) ws[w] = __popc(bal);
        __syncthreads();
        int woff = 0;
#pragma unroll
        for (int i = 0; i < 16; i++) woff += (i < w) ? ws[i] : 0;
        if (v) g_rowidx[offS[b] + woff + pre] = b * Ls + tid;
        __syncthreads();
    }
}

// ---------------- merged split: Q rows (gather, 1/temp) + P rows -----------
__global__ __launch_bounds__(256)
void split_all(const float* __restrict__ Q, const float* __restrict__ P,
               const float* __restrict__ temp)
{
    const int blk = blockIdx.x;
    const int tid = threadIdx.x;

    if (blk < M_) {
        const int cr = blk;
        const int valid  = g_off[B_];
        const int padded = g_off[B_ + 1];
        if (cr >= padded) return;
        __nv_bfloat16* hp = g_Qh + (size_t)cr * D_;
        __nv_bfloat16* lp = g_Ql + (size_t)cr * D_;
        if (cr >= valid) {
#pragma unroll
            for (int j = 0; j < 3; j++) {
                hp[tid + j * 256] = __float2bfloat16(0.f);
                lp[tid + j * 256] = __float2bfloat16(0.f);
            }
            return;
        }
        const float invT = 1.0f / temp[0];
        const float* src = Q + (size_t)g_rowidx[cr] * D_;
#pragma unroll
        for (int j = 0; j < 3; j++) {
            float v = src[tid + j * 256] * invT;
            __nv_bfloat16 h = __float2bfloat16(v);
            hp[tid + j * 256] = h;
            lp[tid + j * 256] = __float2bfloat16(v - __bfloat162float(h));
        }
    } else {
        const int pr = blk - M_;                 // P row 0..Kp-1
        const float* src = P + (size_t)pr * D_;
        __nv_bfloat16* hp = g_Ph + (size_t)pr * D_;
        __nv_bfloat16* lp = g_Pl + (size_t)pr * D_;
#pragma unroll
        for (int j = 0; j < 3; j++) {
            float v = src[tid + j * 256];
            __nv_bfloat16 h = __float2bfloat16(v);
            hp[tid + j * 256] = h;
            lp[tid + j * 256] = __float2bfloat16(v - __bfloat162float(h));
        }
    }
}

// ---------------- HMMA GEMM (proven config, untouched) ----------------------
#define TILE_M 128
#define TILE_N 128
#define BK     32
#define CHUNKS (D_ / BK)       // 24
#define RSTRIDE 40
#define ROWB    (RSTRIDE * 2)
#define TILE_BYTES (128 * ROWB)             // 10240
#define STAGE_BYTES (4 * TILE_BYTES)        // Ah, Al, Bh, Bl
#define SMEM_GEMM   (2 * STAGE_BYTES)       // 81920

__global__ __launch_bounds__(256, 2)
void gemm_mma()
{
    if (blockIdx.x * TILE_M >= g_off[B_ + 1]) return;

    extern __shared__ __align__(16) char smem[];
    const uint32_t sb = smem_u32(smem);

    const int tid  = threadIdx.x;
    const int wid  = tid >> 5, lane = tid & 31;
    const int wm   = wid & 1;
    const int wn   = wid >> 1;
    const int m0   = blockIdx.x * TILE_M;
    const int n0   = blockIdx.y * TILE_N;

    auto load_chunk = [&](int c) {
        const uint32_t stage = sb + (uint32_t)(c & 1) * STAGE_BYTES;
        const int kd0 = c * BK;
#pragma unroll
        for (int it = 0; it < 8; it++) {
            int i    = tid + it * 256;
            int tile = i >> 9;                  // 0:Ah 1:Al 2:Bh 3:Bl
            int r    = (i >> 2) & 127;
            int q    = i & 3;
            uint32_t dst = stage + (uint32_t)tile * TILE_BYTES + r * ROWB + q * 16;
            size_t ge = (size_t)((tile < 2 ? m0 : n0) + r) * D_ + kd0 + q * 8;
            const __nv_bfloat16* src =
                tile == 0 ? g_Qh : tile == 1 ? g_Ql : tile == 2 ? g_Ph : g_Pl;
            cp16(dst, src + ge);
        }
        cp_commit();
    };

    float acc[4][4][4];
#pragma unroll
    for (int i = 0; i < 4; i++)
#pragma unroll
        for (int j = 0; j < 4; j++)
#pragma unroll
            for (int v = 0; v < 4; v++) acc[i][j][v] = 0.f;

    load_chunk(0);
    load_chunk(1);

    for (int c = 0; c < CHUNKS; c++) {
        if (c + 1 < CHUNKS)
            asm volatile("cp.async.wait_group 1;" ::: "memory");
        else
            asm volatile("cp.async.wait_group 0;" ::: "memory");
        __syncthreads();

        const uint32_t stage = sb + (uint32_t)(c & 1) * STAGE_BYTES;
        const uint32_t Ah = stage;
        const uint32_t Al = stage + TILE_BYTES;
        const uint32_t Bh = stage + 2 * TILE_BYTES;
        const uint32_t Bl = stage + 3 * TILE_BYTES;

#pragma unroll
        for (int k16 = 0; k16 < BK; k16 += 16) {
            uint32_t boff = (uint32_t)((wn * 32 + ((lane >> 4) << 3) + (lane & 7)) * ROWB
                                       + (k16 + (((lane >> 3) & 1) << 3)) * 2);
            uint32_t bh[8], bl[8];
            ldm_x4(&bh[0], Bh + boff);
            ldm_x4(&bh[4], Bh + boff + 16 * ROWB);
            ldm_x4(&bl[0], Bl + boff);
            ldm_x4(&bl[4], Bl + boff + 16 * ROWB);

            uint32_t aoff = (uint32_t)((wm * 64 + (lane & 15)) * ROWB
                                       + (k16 + ((lane >> 4) << 3)) * 2);
#pragma unroll
            for (int mt = 0; mt < 4; mt++) {
                uint32_t ah[4], al[4];
                ldm_x4(ah, Ah + aoff + mt * 16 * ROWB);
                ldm_x4(al, Al + aoff + mt * 16 * ROWB);
#pragma unroll
                for (int nt = 0; nt < 4; nt++) {
                    mma16816(acc[mt][nt], ah, &bh[nt * 2]);
                    mma16816(acc[mt][nt], ah, &bl[nt * 2]);
                    mma16816(acc[mt][nt], al, &bh[nt * 2]);
                }
            }
        }
        __syncthreads();
        if (c + 2 < CHUNKS) load_chunk(c + 2);
    }

    const int rbase = m0 + wm * 64 + (lane >> 2);
    const int cbase = n0 + wn * 32 + (lane & 3) * 2;
#pragma unroll
    for (int mt = 0; mt < 4; mt++) {
#pragma unroll
        for (int nt = 0; nt < 4; nt++) {
            float* p0 = &g_logits[(size_t)(rbase + mt * 16) * Kp + cbase + nt * 8];
            float* p1 = &g_logits[(size_t)(rbase + mt * 16 + 8) * Kp + cbase + nt * 8];
            *reinterpret_cast<float2*>(p0) = make_float2(acc[mt][nt][0], acc[mt][nt][1]);
            *reinterpret_cast<float2*>(p1) = make_float2(acc[mt][nt][2], acc[mt][nt][3]);
        }
    }
}

// ---------------- single-pass online row stats: c = m + log(sum exp) --------
__global__ __launch_bounds__(256)
void row_stats()
{
    const int row = blockIdx.x;
    if (row >= g_off[B_]) return;
    const float* Lr = g_logits + (size_t)row * Kp;
    const int tid = threadIdx.x;

    float m = -INFINITY, s = 0.f;
#pragma unroll
    for (int j = 0; j < 8; j++) {
        float4 v = *reinterpret_cast<const float4*>(&Lr[(tid + j * 256) * 4]);
        float lm = fmaxf(fmaxf(v.x, v.y), fmaxf(v.z, v.w));
        if (lm > m) { s *= expf(m - lm); m = lm; }
        s += expf(v.x - m) + expf(v.y - m) + expf(v.z - m) + expf(v.w - m);
    }
#pragma unroll
    for (int off = 16; off; off >>= 1) {
        float om = __shfl_xor_sync(0xffffffffu, m, off);
        float os = __shfl_xor_sync(0xffffffffu, s, off);
        float nm = fmaxf(m, om);
        s = s * expf(m - nm) + os * expf(om - nm);
        m = nm;
    }
    __shared__ float shm[8], shs[8];
    if ((tid & 31) == 0) { shm[tid >> 5] = m; shs[tid >> 5] = s; }
    __syncthreads();
    if (tid == 0) {
        float fm = shm[0], fs = shs[0];
#pragma unroll
        for (int w = 1; w < 8; w++) {
            float nm = fmaxf(fm, shm[w]);
            fs = fs * expf(fm - nm) + shs[w] * expf(shm[w] - nm);
            fm = nm;
        }
        g_c[row] = fm + logf(fs);
    }
}

// ---------------- column max over valid rows, exp into out ------------------
__global__ __launch_bounds__(256)
void col_max(float* __restrict__ out)
{
    const int b   = blockIdx.y;
    const int k   = blockIdx.x * 256 + threadIdx.x;
    const int tid = threadIdx.x;
    const int lo  = g_off[b], hi = g_off[b + 1];
    const int cnt = hi - lo;

    __shared__ float cs[Ls];
    for (int i = tid; i < cnt; i += 256) cs[i] = g_c[lo + i];
    __syncthreads();

    const float* base = g_logits + (size_t)lo * Kp + k;
    float t = -INFINITY;
    for (int i = 0; i < cnt; i++)
        t = fmaxf(t, base[(size_t)i * Kp] - cs[i]);

    out[b * Kp + k] = (cnt > 0) ? expf(t) : 0.f;
}

// ---------------- L2 normalize ----------------------------------------------
__device__ __forceinline__ float warpSum(float v) {
#pragma unroll
    for (int o = 16; o; o >>= 1) v += __shfl_xor_sync(0xffffffffu, v, o);
    return v;
}

__global__ __launch_bounds__(256)
void l2norm(float* __restrict__ out)
{
    const int b = blockIdx.x;
    float* o = out + b * Kp;
    const int tid = threadIdx.x;
    __shared__ float sh[8];
    __shared__ float bc;

    float s = 0.f;
    for (int i = tid; i < Kp; i += 256) { float v = o[i]; s = fmaf(v, v, s); }
    s = warpSum(s);
    if ((tid & 31) == 0) sh[tid >> 5] = s;
    __syncthreads();
    if (tid == 0) {
        float t = 0.f;
#pragma unroll
        for (int w = 0; w < 8; w++) t += sh[w];
        bc = 1.0f / fmaxf(sqrtf(t), 1e-12f);
    }
    __syncthreads();
    const float sc = bc;
    for (int i = tid; i < Kp; i += 256) o[i] *= sc;
}

// ---------------- launch (single stream) ------------------------------------
extern "C" void kernel_launch(void* const* d_in, const int* in_sizes, int n_in,
                              void* d_out, int out_size)
{
    const float* Q    = (const float*)d_in[0];
    const float* P    = (const float*)d_in[1];
    const float* temp = (const float*)d_in[2];
    const int*   mask = (const int*)d_in[3];
    float* out = (float*)d_out;

    cudaFuncSetAttribute(gemm_mma, cudaFuncAttributeMaxDynamicSharedMemorySize,
                         SMEM_GEMM);

    mask_all<<<1, Ls>>>(mask);                   // fused scan+offsets+scatter

    split_all<<<M_ + Kp, 256>>>(Q, P, temp);     // Q rows + P rows in one grid

    dim3 gGemm(M_ / TILE_M, Kp / TILE_N);        // (128, 64); empty m-tiles exit
    gemm_mma<<<gGemm, 256, SMEM_GEMM>>>();

    row_stats<<<M_, 256>>>();
    dim3 gCol(Kp / 256, B_);
    col_max<<<gCol, 256>>>(out);
    l2norm<<<B_, 256>>>(out);
}

// round 16
// speedup vs baseline: 1.0185x; 1.0185x over previous
#include <cuda_runtime.h>
#include <cuda_bf16.h>
#include <math.h>
#include <stdint.h>

// Problem shape (fixed)
#define B_  32
#define Ls  512
#define D_  768
#define Kp  8192
#define M_  (B_ * Ls)        // 16384

// ---------------- device scratch (allocation-free) -------------------------
__device__ float g_logits[(size_t)M_ * Kp];           // fp32 logits (compact rows)
__device__ float g_c[M_];                             // per-row m + log(sum exp)
__device__ __nv_bfloat16 g_Qh[(size_t)M_ * D_];
__device__ __nv_bfloat16 g_Ql[(size_t)M_ * D_];
__device__ __nv_bfloat16 g_Ph[(size_t)Kp * D_];
__device__ __nv_bfloat16 g_Pl[(size_t)Kp * D_];
__device__ int g_cnt[B_];
__device__ int g_local[M_];
__device__ int g_off[B_ + 2];        // [0..32] offsets; [32]=valid; [33]=padded
__device__ int g_rowidx[M_];

// ---------------- PTX helpers ------------------------------------------------
__device__ __forceinline__ uint32_t smem_u32(const void* p) {
    uint32_t a;
    asm("{ .reg .u64 t; cvta.to.shared.u64 t, %1; cvt.u32.u64 %0, t; }"
        : "=r"(a) : "l"(p));
    return a;
}
__device__ __forceinline__ void cp16(uint32_t dst, const void* src) {
    asm volatile("cp.async.cg.shared.global [%0], [%1], 16;" :: "r"(dst), "l"(src));
}
__device__ __forceinline__ void cp_commit() {
    asm volatile("cp.async.commit_group;" ::: "memory");
}
__device__ __forceinline__ void ldm_x4(uint32_t* r, uint32_t addr) {
    asm volatile("ldmatrix.sync.aligned.m8n8.x4.shared.b16 {%0,%1,%2,%3}, [%4];"
                 : "=r"(r[0]), "=r"(r[1]), "=r"(r[2]), "=r"(r[3]) : "r"(addr));
}
__device__ __forceinline__ void mma16816(float* c, const uint32_t* a, const uint32_t* b) {
    asm volatile(
        "mma.sync.aligned.m16n8k16.row.col.f32.bf16.bf16.f32 "
        "{%0,%1,%2,%3}, {%4,%5,%6,%7}, {%8,%9}, {%0,%1,%2,%3};"
        : "+f"(c[0]), "+f"(c[1]), "+f"(c[2]), "+f"(c[3])
        : "r"(a[0]), "r"(a[1]), "r"(a[2]), "r"(a[3]), "r"(b[0]), "r"(b[1]));
}

// ---------------- mask compaction (3-kernel chain, proven) ------------------
__global__ __launch_bounds__(Ls)
void mask_scan(const int* __restrict__ mask)
{
    const int b = blockIdx.x, l = threadIdx.x;
    const int lane = l & 31, w = l >> 5;
    const int v = mask[b * Ls + l] ? 1 : 0;
    const unsigned bal = __ballot_sync(0xffffffffu, v);
    const int pre = __popc(bal & ((1u << lane) - 1u));
    __shared__ int ws[16];
    if (lane == 0) ws[w] = __popc(bal);
    __syncthreads();
    int woff = 0;
#pragma unroll
    for (int i = 0; i < 16; i++) woff += (i < w) ? ws[i] : 0;
    g_local[b * Ls + l] = woff + pre;
    if (l == Ls - 1) g_cnt[b] = woff + pre + v;
}

__global__ void scan_offsets()
{
    const int t = threadIdx.x;            // 0..31
    int x = g_cnt[t];
#pragma unroll
    for (int o = 1; o < 32; o <<= 1) {
        int y = __shfl_up_sync(0xffffffffu, x, o);
        if (t >= o) x += y;
    }
    g_off[t + 1] = x;
    if (t == 0) g_off[0] = 0;
    if (t == 31) g_off[B_ + 1] = (x + 127) & ~127;   // padded total (TILE_M=128)
}

__global__ __launch_bounds__(Ls)
void scatter_idx(const int* __restrict__ mask)
{
    const int b = blockIdx.x, l = threadIdx.x;
    if (mask[b * Ls + l])
        g_rowidx[g_off[b] + g_local[b * Ls + l]] = b * Ls + l;
}

// ---------------- merged split, vectorized (float4 in, bf16x2 out) ----------
// blocks [0, M_)       : compact Q row (gather, 1/temp folded)
// blocks [M_, M_+Kp)   : P row
// 192 active threads/row: one float4 load, two uint2 stores (hi, lo).
__device__ __forceinline__ uint2 split4(float4 v, float scale,
                                        uint2& lo_out)
{
    float x0 = v.x * scale, x1 = v.y * scale, x2 = v.z * scale, x3 = v.w * scale;
    __nv_bfloat16 h0 = __float2bfloat16(x0);
    __nv_bfloat16 h1 = __float2bfloat16(x1);
    __nv_bfloat16 h2 = __float2bfloat16(x2);
    __nv_bfloat16 h3 = __float2bfloat16(x3);
    __nv_bfloat16 l0 = __float2bfloat16(x0 - __bfloat162float(h0));
    __nv_bfloat16 l1 = __float2bfloat16(x1 - __bfloat162float(h1));
    __nv_bfloat16 l2 = __float2bfloat16(x2 - __bfloat162float(h2));
    __nv_bfloat16 l3 = __float2bfloat16(x3 - __bfloat162float(h3));
    __nv_bfloat162 hp01 = __nv_bfloat162(h0, h1), hp23 = __nv_bfloat162(h2, h3);
    __nv_bfloat162 lp01 = __nv_bfloat162(l0, l1), lp23 = __nv_bfloat162(l2, l3);
    uint2 hi_out;
    hi_out.x = *reinterpret_cast<uint32_t*>(&hp01);
    hi_out.y = *reinterpret_cast<uint32_t*>(&hp23);
    lo_out.x = *reinterpret_cast<uint32_t*>(&lp01);
    lo_out.y = *reinterpret_cast<uint32_t*>(&lp23);
    return hi_out;
}

__global__ __launch_bounds__(192)
void split_all(const float* __restrict__ Q, const float* __restrict__ P,
               const float* __restrict__ temp)
{
    const int blk = blockIdx.x;
    const int tid = threadIdx.x;         // 0..191 (768/4)

    if (blk < M_) {
        const int cr = blk;
        const int valid  = g_off[B_];
        const int padded = g_off[B_ + 1];
        if (cr >= padded) return;
        uint2* hp = reinterpret_cast<uint2*>(g_Qh + (size_t)cr * D_);
        uint2* lp = reinterpret_cast<uint2*>(g_Ql + (size_t)cr * D_);
        if (cr >= valid) {
            hp[tid] = make_uint2(0u, 0u);
            lp[tid] = make_uint2(0u, 0u);
            return;
        }
        const float invT = 1.0f / temp[0];
        const float4* src = reinterpret_cast<const float4*>(
            Q + (size_t)g_rowidx[cr] * D_);
        uint2 lo;
        uint2 hi = split4(src[tid], invT, lo);
        hp[tid] = hi;
        lp[tid] = lo;
    } else {
        const int pr = blk - M_;
        const float4* src = reinterpret_cast<const float4*>(P + (size_t)pr * D_);
        uint2* hp = reinterpret_cast<uint2*>(g_Ph + (size_t)pr * D_);
        uint2* lp = reinterpret_cast<uint2*>(g_Pl + (size_t)pr * D_);
        uint2 lo;
        uint2 hi = split4(src[tid], 1.0f, lo);
        hp[tid] = hi;
        lp[tid] = lo;
    }
}

// ---------------- HMMA GEMM (proven config, untouched) ----------------------
#define TILE_M 128
#define TILE_N 128
#define BK     32
#define CHUNKS (D_ / BK)       // 24
#define RSTRIDE 40
#define ROWB    (RSTRIDE * 2)
#define TILE_BYTES (128 * ROWB)             // 10240
#define STAGE_BYTES (4 * TILE_BYTES)        // Ah, Al, Bh, Bl
#define SMEM_GEMM   (2 * STAGE_BYTES)       // 81920

__global__ __launch_bounds__(256, 2)
void gemm_mma()
{
    if (blockIdx.x * TILE_M >= g_off[B_ + 1]) return;

    extern __shared__ __align__(16) char smem[];
    const uint32_t sb = smem_u32(smem);

    const int tid  = threadIdx.x;
    const int wid  = tid >> 5, lane = tid & 31;
    const int wm   = wid & 1;
    const int wn   = wid >> 1;
    const int m0   = blockIdx.x * TILE_M;
    const int n0   = blockIdx.y * TILE_N;

    auto load_chunk = [&](int c) {
        const uint32_t stage = sb + (uint32_t)(c & 1) * STAGE_BYTES;
        const int kd0 = c * BK;
#pragma unroll
        for (int it = 0; it < 8; it++) {
            int i    = tid + it * 256;
            int tile = i >> 9;                  // 0:Ah 1:Al 2:Bh 3:Bl
            int r    = (i >> 2) & 127;
            int q    = i & 3;
            uint32_t dst = stage + (uint32_t)tile * TILE_BYTES + r * ROWB + q * 16;
            size_t ge = (size_t)((tile < 2 ? m0 : n0) + r) * D_ + kd0 + q * 8;
            const __nv_bfloat16* src =
                tile == 0 ? g_Qh : tile == 1 ? g_Ql : tile == 2 ? g_Ph : g_Pl;
            cp16(dst, src + ge);
        }
        cp_commit();
    };

    float acc[4][4][4];
#pragma unroll
    for (int i = 0; i < 4; i++)
#pragma unroll
        for (int j = 0; j < 4; j++)
#pragma unroll
            for (int v = 0; v < 4; v++) acc[i][j][v] = 0.f;

    load_chunk(0);
    load_chunk(1);

    for (int c = 0; c < CHUNKS; c++) {
        if (c + 1 < CHUNKS)
            asm volatile("cp.async.wait_group 1;" ::: "memory");
        else
            asm volatile("cp.async.wait_group 0;" ::: "memory");
        __syncthreads();

        const uint32_t stage = sb + (uint32_t)(c & 1) * STAGE_BYTES;
        const uint32_t Ah = stage;
        const uint32_t Al = stage + TILE_BYTES;
        const uint32_t Bh = stage + 2 * TILE_BYTES;
        const uint32_t Bl = stage + 3 * TILE_BYTES;

#pragma unroll
        for (int k16 = 0; k16 < BK; k16 += 16) {
            uint32_t boff = (uint32_t)((wn * 32 + ((lane >> 4) << 3) + (lane & 7)) * ROWB
                                       + (k16 + (((lane >> 3) & 1) << 3)) * 2);
            uint32_t bh[8], bl[8];
            ldm_x4(&bh[0], Bh + boff);
            ldm_x4(&bh[4], Bh + boff + 16 * ROWB);
            ldm_x4(&bl[0], Bl + boff);
            ldm_x4(&bl[4], Bl + boff + 16 * ROWB);

            uint32_t aoff = (uint32_t)((wm * 64 + (lane & 15)) * ROWB
                                       + (k16 + ((lane >> 4) << 3)) * 2);
#pragma unroll
            for (int mt = 0; mt < 4; mt++) {
                uint32_t ah[4], al[4];
                ldm_x4(ah, Ah + aoff + mt * 16 * ROWB);
                ldm_x4(al, Al + aoff + mt * 16 * ROWB);
#pragma unroll
                for (int nt = 0; nt < 4; nt++) {
                    mma16816(acc[mt][nt], ah, &bh[nt * 2]);
                    mma16816(acc[mt][nt], ah, &bl[nt * 2]);
                    mma16816(acc[mt][nt], al, &bh[nt * 2]);
                }
            }
        }
        __syncthreads();
        if (c + 2 < CHUNKS) load_chunk(c + 2);
    }

    const int rbase = m0 + wm * 64 + (lane >> 2);
    const int cbase = n0 + wn * 32 + (lane & 3) * 2;
#pragma unroll
    for (int mt = 0; mt < 4; mt++) {
#pragma unroll
        for (int nt = 0; nt < 4; nt++) {
            float* p0 = &g_logits[(size_t)(rbase + mt * 16) * Kp + cbase + nt * 8];
            float* p1 = &g_logits[(size_t)(rbase + mt * 16 + 8) * Kp + cbase + nt * 8];
            *reinterpret_cast<float2*>(p0) = make_float2(acc[mt][nt][0], acc[mt][nt][1]);
            *reinterpret_cast<float2*>(p1) = make_float2(acc[mt][nt][2], acc[mt][nt][3]);
        }
    }
}

// ---------------- single-pass online row stats: c = m + log(sum exp) --------
__global__ __launch_bounds__(256)
void row_stats()
{
    const int row = blockIdx.x;
    if (row >= g_off[B_]) return;
    const float* Lr = g_logits + (size_t)row * Kp;
    const int tid = threadIdx.x;

    float m = -INFINITY, s = 0.f;
#pragma unroll
    for (int j = 0; j < 8; j++) {
        float4 v = *reinterpret_cast<const float4*>(&Lr[(tid + j * 256) * 4]);
        float lm = fmaxf(fmaxf(v.x, v.y), fmaxf(v.z, v.w));
        if (lm > m) { s *= expf(m - lm); m = lm; }
        s += expf(v.x - m) + expf(v.y - m) + expf(v.z - m) + expf(v.w - m);
    }
#pragma unroll
    for (int off = 16; off; off >>= 1) {
        float om = __shfl_xor_sync(0xffffffffu, m, off);
        float os = __shfl_xor_sync(0xffffffffu, s, off);
        float nm = fmaxf(m, om);
        s = s * expf(m - nm) + os * expf(om - nm);
        m = nm;
    }
    __shared__ float shm[8], shs[8];
    if ((tid & 31) == 0) { shm[tid >> 5] = m; shs[tid >> 5] = s; }
    __syncthreads();
    if (tid == 0) {
        float fm = shm[0], fs = shs[0];
#pragma unroll
        for (int w = 1; w < 8; w++) {
            float nm = fmaxf(fm, shm[w]);
            fs = fs * expf(fm - nm) + shs[w] * expf(shm[w] - nm);
            fm = nm;
        }
        g_c[row] = fm + logf(fs);
    }
}

// ---------------- column max over valid rows, exp into out ------------------
__global__ __launch_bounds__(256)
void col_max(float* __restrict__ out)
{
    const int b   = blockIdx.y;
    const int k   = blockIdx.x * 256 + threadIdx.x;
    const int tid = threadIdx.x;
    const int lo  = g_off[b], hi = g_off[b + 1];
    const int cnt = hi - lo;

    __shared__ float cs[Ls];
    for (int i = tid; i < cnt; i += 256) cs[i] = g_c[lo + i];
    __syncthreads();

    const float* base = g_logits + (size_t)lo * Kp + k;
    float t = -INFINITY;
    for (int i = 0; i < cnt; i++)
        t = fmaxf(t, base[(size_t)i * Kp] - cs[i]);

    out[b * Kp + k] = (cnt > 0) ? expf(t) : 0.f;
}

// ---------------- L2 normalize ----------------------------------------------
__device__ __forceinline__ float warpSum(float v) {
#pragma unroll
    for (int o = 16; o; o >>= 1) v += __shfl_xor_sync(0xffffffffu, v, o);
    return v;
}

__global__ __launch_bounds__(256)
void l2norm(float* __restrict__ out)
{
    const int b = blockIdx.x;
    float* o = out + b * Kp;
    const int tid = threadIdx.x;
    __shared__ float sh[8];
    __shared__ float bc;

    float s = 0.f;
    for (int i = tid; i < Kp; i += 256) { float v = o[i]; s = fmaf(v, v, s); }
    s = warpSum(s);
    if ((tid & 31) == 0) sh[tid >> 5] = s;
    __syncthreads();
    if (tid == 0) {
        float t = 0.f;
#pragma unroll
        for (int w = 0; w < 8; w++) t += sh[w];
        bc = 1.0f / fmaxf(sqrtf(t), 1e-12f);
    }
    __syncthreads();
    const float sc = bc;
    for (int i = tid; i < Kp; i += 256) o[i] *= sc;
}

// ---------------- launch (single stream, R14 structure) ---------------------
extern "C" void kernel_launch(void* const* d_in, const int* in_sizes, int n_in,
                              void* d_out, int out_size)
{
    const float* Q    = (const float*)d_in[0];
    const float* P    = (const float*)d_in[1];
    const float* temp = (const float*)d_in[2];
    const int*   mask = (const int*)d_in[3];
    float* out = (float*)d_out;

    cudaFuncSetAttribute(gemm_mma, cudaFuncAttributeMaxDynamicSharedMemorySize,
                         SMEM_GEMM);

    mask_scan<<<B_, Ls>>>(mask);
    scan_offsets<<<1, 32>>>();
    scatter_idx<<<B_, Ls>>>(mask);

    split_all<<<M_ + Kp, 192>>>(Q, P, temp);     // Q rows + P rows, vectorized

    dim3 gGemm(M_ / TILE_M, Kp / TILE_N);        // (128, 64); empty m-tiles exit
    gemm_mma<<<gGemm, 256, SMEM_GEMM>>>();

    row_stats<<<M_, 256>>>();
    dim3 gCol(Kp / 256, B_);
    col_max<<<gCol, 256>>>(out);
    l2norm<<<B_, 256>>>(out);
}

// round 17
// speedup vs baseline: 1.0214x; 1.0029x over previous
#include <cuda_runtime.h>
#include <cuda_bf16.h>
#include <math.h>
#include <stdint.h>

// Problem shape (fixed)
#define B_  32
#define Ls  512
#define D_  768
#define Kp  8192
#define M_  (B_ * Ls)        // 16384

// ---------------- device scratch (allocation-free) -------------------------
__device__ float g_logits[(size_t)M_ * Kp];           // log2-domain logits
__device__ float g_c[M_];                             // per-row m + log2(sum 2^)
__device__ __nv_bfloat16 g_Qh[(size_t)M_ * D_];
__device__ __nv_bfloat16 g_Ql[(size_t)M_ * D_];
__device__ __nv_bfloat16 g_Ph[(size_t)Kp * D_];
__device__ __nv_bfloat16 g_Pl[(size_t)Kp * D_];
__device__ int g_cnt[B_];
__device__ int g_local[M_];
__device__ int g_off[B_ + 2];        // [0..32] offsets; [32]=valid; [33]=padded
__device__ int g_rowidx[M_];

#define LOG2E 1.4426950408889634f

// ---------------- PTX helpers ------------------------------------------------
__device__ __forceinline__ uint32_t smem_u32(const void* p) {
    uint32_t a;
    asm("{ .reg .u64 t; cvta.to.shared.u64 t, %1; cvt.u32.u64 %0, t; }"
        : "=r"(a) : "l"(p));
    return a;
}
__device__ __forceinline__ void cp16(uint32_t dst, const void* src) {
    asm volatile("cp.async.cg.shared.global [%0], [%1], 16;" :: "r"(dst), "l"(src));
}
__device__ __forceinline__ void cp_commit() {
    asm volatile("cp.async.commit_group;" ::: "memory");
}
__device__ __forceinline__ void ldm_x4(uint32_t* r, uint32_t addr) {
    asm volatile("ldmatrix.sync.aligned.m8n8.x4.shared.b16 {%0,%1,%2,%3}, [%4];"
                 : "=r"(r[0]), "=r"(r[1]), "=r"(r[2]), "=r"(r[3]) : "r"(addr));
}
__device__ __forceinline__ void mma16816(float* c, const uint32_t* a, const uint32_t* b) {
    asm volatile(
        "mma.sync.aligned.m16n8k16.row.col.f32.bf16.bf16.f32 "
        "{%0,%1,%2,%3}, {%4,%5,%6,%7}, {%8,%9}, {%0,%1,%2,%3};"
        : "+f"(c[0]), "+f"(c[1]), "+f"(c[2]), "+f"(c[3])
        : "r"(a[0]), "r"(a[1]), "r"(a[2]), "r"(a[3]), "r"(b[0]), "r"(b[1]));
}

// ---------------- mask compaction (2 kernels: scan + fused offsets/scatter) --
__global__ __launch_bounds__(Ls)
void mask_scan(const int* __restrict__ mask)
{
    const int b = blockIdx.x, l = threadIdx.x;
    const int lane = l & 31, w = l >> 5;
    const int v = mask[b * Ls + l] ? 1 : 0;
    const unsigned bal = __ballot_sync(0xffffffffu, v);
    const int pre = __popc(bal & ((1u << lane) - 1u));
    __shared__ int ws[16];
    if (lane == 0) ws[w] = __popc(bal);
    __syncthreads();
    int woff = 0;
#pragma unroll
    for (int i = 0; i < 16; i++) woff += (i < w) ? ws[i] : 0;
    g_local[b * Ls + l] = woff + pre;
    if (l == Ls - 1) g_cnt[b] = woff + pre + v;
}

// fused: every block scans the 32 counts (warp 0) -> smem; block 0 writes g_off
__global__ __launch_bounds__(Ls)
void scatter_idx(const int* __restrict__ mask)
{
    const int b = blockIdx.x, l = threadIdx.x;
    __shared__ int offS;                   // exclusive offset of batch b

    if (l < 32) {
        int x = g_cnt[l];
#pragma unroll
        for (int o = 1; o < 32; o <<= 1) {
            int y = __shfl_up_sync(0xffffffffu, x, o);
            if (l >= o) x += y;
        }
        // x = inclusive prefix; exclusive offset of batch b = incl[b-1]
        if (l == b) offS = x - g_cnt[b];
        if (b == 0) {
            g_off[l + 1] = x;
            if (l == 0) g_off[0] = 0;
            if (l == 31) g_off[B_ + 1] = (x + 127) & ~127;   // padded
        }
    }
    __syncthreads();

    if (mask[b * Ls + l])
        g_rowidx[offS + g_local[b * Ls + l]] = b * Ls + l;
}

// ---------------- merged split, vectorized (float4 in, bf16x2 out) ----------
// Q rows get (1/temp)*log2(e) folded in -> logits live in log2 domain.
__device__ __forceinline__ uint2 split4(float4 v, float scale, uint2& lo_out)
{
    float x0 = v.x * scale, x1 = v.y * scale, x2 = v.z * scale, x3 = v.w * scale;
    __nv_bfloat16 h0 = __float2bfloat16(x0);
    __nv_bfloat16 h1 = __float2bfloat16(x1);
    __nv_bfloat16 h2 = __float2bfloat16(x2);
    __nv_bfloat16 h3 = __float2bfloat16(x3);
    __nv_bfloat16 l0 = __float2bfloat16(x0 - __bfloat162float(h0));
    __nv_bfloat16 l1 = __float2bfloat16(x1 - __bfloat162float(h1));
    __nv_bfloat16 l2 = __float2bfloat16(x2 - __bfloat162float(h2));
    __nv_bfloat16 l3 = __float2bfloat16(x3 - __bfloat162float(h3));
    __nv_bfloat162 hp01 = __nv_bfloat162(h0, h1), hp23 = __nv_bfloat162(h2, h3);
    __nv_bfloat162 lp01 = __nv_bfloat162(l0, l1), lp23 = __nv_bfloat162(l2, l3);
    uint2 hi_out;
    hi_out.x = *reinterpret_cast<uint32_t*>(&hp01);
    hi_out.y = *reinterpret_cast<uint32_t*>(&hp23);
    lo_out.x = *reinterpret_cast<uint32_t*>(&lp01);
    lo_out.y = *reinterpret_cast<uint32_t*>(&lp23);
    return hi_out;
}

__global__ __launch_bounds__(192)
void split_all(const float* __restrict__ Q, const float* __restrict__ P,
               const float* __restrict__ temp)
{
    const int blk = blockIdx.x;
    const int tid = threadIdx.x;         // 0..191 (768/4)

    if (blk < M_) {
        const int cr = blk;
        const int valid  = g_off[B_];
        const int padded = g_off[B_ + 1];
        if (cr >= padded) return;
        uint2* hp = reinterpret_cast<uint2*>(g_Qh + (size_t)cr * D_);
        uint2* lp = reinterpret_cast<uint2*>(g_Ql + (size_t)cr * D_);
        if (cr >= valid) {
            hp[tid] = make_uint2(0u, 0u);
            lp[tid] = make_uint2(0u, 0u);
            return;
        }
        const float invT = LOG2E / temp[0];      // log2-domain fold
        const float4* src = reinterpret_cast<const float4*>(
            Q + (size_t)g_rowidx[cr] * D_);
        uint2 lo;
        uint2 hi = split4(src[tid], invT, lo);
        hp[tid] = hi;
        lp[tid] = lo;
    } else {
        const int pr = blk - M_;
        const float4* src = reinterpret_cast<const float4*>(P + (size_t)pr * D_);
        uint2* hp = reinterpret_cast<uint2*>(g_Ph + (size_t)pr * D_);
        uint2* lp = reinterpret_cast<uint2*>(g_Pl + (size_t)pr * D_);
        uint2 lo;
        uint2 hi = split4(src[tid], 1.0f, lo);
        hp[tid] = hi;
        lp[tid] = lo;
    }
}

// ---------------- HMMA GEMM (proven config, untouched) ----------------------
#define TILE_M 128
#define TILE_N 128
#define BK     32
#define CHUNKS (D_ / BK)       // 24
#define RSTRIDE 40
#define ROWB    (RSTRIDE * 2)
#define TILE_BYTES (128 * ROWB)             // 10240
#define STAGE_BYTES (4 * TILE_BYTES)        // Ah, Al, Bh, Bl
#define SMEM_GEMM   (2 * STAGE_BYTES)       // 81920

__global__ __launch_bounds__(256, 2)
void gemm_mma()
{
    if (blockIdx.x * TILE_M >= g_off[B_ + 1]) return;

    extern __shared__ __align__(16) char smem[];
    const uint32_t sb = smem_u32(smem);

    const int tid  = threadIdx.x;
    const int wid  = tid >> 5, lane = tid & 31;
    const int wm   = wid & 1;
    const int wn   = wid >> 1;
    const int m0   = blockIdx.x * TILE_M;
    const int n0   = blockIdx.y * TILE_N;

    auto load_chunk = [&](int c) {
        const uint32_t stage = sb + (uint32_t)(c & 1) * STAGE_BYTES;
        const int kd0 = c * BK;
#pragma unroll
        for (int it = 0; it < 8; it++) {
            int i    = tid + it * 256;
            int tile = i >> 9;                  // 0:Ah 1:Al 2:Bh 3:Bl
            int r    = (i >> 2) & 127;
            int q    = i & 3;
            uint32_t dst = stage + (uint32_t)tile * TILE_BYTES + r * ROWB + q * 16;
            size_t ge = (size_t)((tile < 2 ? m0 : n0) + r) * D_ + kd0 + q * 8;
            const __nv_bfloat16* src =
                tile == 0 ? g_Qh : tile == 1 ? g_Ql : tile == 2 ? g_Ph : g_Pl;
            cp16(dst, src + ge);
        }
        cp_commit();
    };

    float acc[4][4][4];
#pragma unroll
    for (int i = 0; i < 4; i++)
#pragma unroll
        for (int j = 0; j < 4; j++)
#pragma unroll
            for (int v = 0; v < 4; v++) acc[i][j][v] = 0.f;

    load_chunk(0);
    load_chunk(1);

    for (int c = 0; c < CHUNKS; c++) {
        if (c + 1 < CHUNKS)
            asm volatile("cp.async.wait_group 1;" ::: "memory");
        else
            asm volatile("cp.async.wait_group 0;" ::: "memory");
        __syncthreads();

        const uint32_t stage = sb + (uint32_t)(c & 1) * STAGE_BYTES;
        const uint32_t Ah = stage;
        const uint32_t Al = stage + TILE_BYTES;
        const uint32_t Bh = stage + 2 * TILE_BYTES;
        const uint32_t Bl = stage + 3 * TILE_BYTES;

#pragma unroll
        for (int k16 = 0; k16 < BK; k16 += 16) {
            uint32_t boff = (uint32_t)((wn * 32 + ((lane >> 4) << 3) + (lane & 7)) * ROWB
                                       + (k16 + (((lane >> 3) & 1) << 3)) * 2);
            uint32_t bh[8], bl[8];
            ldm_x4(&bh[0], Bh + boff);
            ldm_x4(&bh[4], Bh + boff + 16 * ROWB);
            ldm_x4(&bl[0], Bl + boff);
            ldm_x4(&bl[4], Bl + boff + 16 * ROWB);

            uint32_t aoff = (uint32_t)((wm * 64 + (lane & 15)) * ROWB
                                       + (k16 + ((lane >> 4) << 3)) * 2);
#pragma unroll
            for (int mt = 0; mt < 4; mt++) {
                uint32_t ah[4], al[4];
                ldm_x4(ah, Ah + aoff + mt * 16 * ROWB);
                ldm_x4(al, Al + aoff + mt * 16 * ROWB);
#pragma unroll
                for (int nt = 0; nt < 4; nt++) {
                    mma16816(acc[mt][nt], ah, &bh[nt * 2]);
                    mma16816(acc[mt][nt], ah, &bl[nt * 2]);
                    mma16816(acc[mt][nt], al, &bh[nt * 2]);
                }
            }
        }
        __syncthreads();
        if (c + 2 < CHUNKS) load_chunk(c + 2);
    }

    const int rbase = m0 + wm * 64 + (lane >> 2);
    const int cbase = n0 + wn * 32 + (lane & 3) * 2;
#pragma unroll
    for (int mt = 0; mt < 4; mt++) {
#pragma unroll
        for (int nt = 0; nt < 4; nt++) {
            float* p0 = &g_logits[(size_t)(rbase + mt * 16) * Kp + cbase + nt * 8];
            float* p1 = &g_logits[(size_t)(rbase + mt * 16 + 8) * Kp + cbase + nt * 8];
            *reinterpret_cast<float2*>(p0) = make_float2(acc[mt][nt][0], acc[mt][nt][1]);
            *reinterpret_cast<float2*>(p1) = make_float2(acc[mt][nt][2], acc[mt][nt][3]);
        }
    }
}

// ---------------- single-pass online row stats (log2 domain) ----------------
__global__ __launch_bounds__(256)
void row_stats()
{
    const int row = blockIdx.x;
    if (row >= g_off[B_]) return;
    const float* Lr = g_logits + (size_t)row * Kp;
    const int tid = threadIdx.x;

    float m = -INFINITY, s = 0.f;
#pragma unroll
    for (int j = 0; j < 8; j++) {
        float4 v = *reinterpret_cast<const float4*>(&Lr[(tid + j * 256) * 4]);
        float lm = fmaxf(fmaxf(v.x, v.y), fmaxf(v.z, v.w));
        if (lm > m) { s *= exp2f(m - lm); m = lm; }
        s += exp2f(v.x - m) + exp2f(v.y - m) + exp2f(v.z - m) + exp2f(v.w - m);
    }
#pragma unroll
    for (int off = 16; off; off >>= 1) {
        float om = __shfl_xor_sync(0xffffffffu, m, off);
        float os = __shfl_xor_sync(0xffffffffu, s, off);
        float nm = fmaxf(m, om);
        s = s * exp2f(m - nm) + os * exp2f(om - nm);
        m = nm;
    }
    __shared__ float shm[8], shs[8];
    if ((tid & 31) == 0) { shm[tid >> 5] = m; shs[tid >> 5] = s; }
    __syncthreads();
    if (tid == 0) {
        float fm = shm[0], fs = shs[0];
#pragma unroll
        for (int w = 1; w < 8; w++) {
            float nm = fmaxf(fm, shm[w]);
            fs = fs * exp2f(fm - nm) + shs[w] * exp2f(shm[w] - nm);
            fm = nm;
        }
        g_c[row] = fm + log2f(fs);
    }
}

// ---------------- column max over valid rows, exp2 into out -----------------
__global__ __launch_bounds__(256)
void col_max(float* __restrict__ out)
{
    const int b   = blockIdx.y;
    const int k   = blockIdx.x * 256 + threadIdx.x;
    const int tid = threadIdx.x;
    const int lo  = g_off[b], hi = g_off[b + 1];
    const int cnt = hi - lo;

    __shared__ float cs[Ls];
    for (int i = tid; i < cnt; i += 256) cs[i] = g_c[lo + i];
    __syncthreads();

    const float* base = g_logits + (size_t)lo * Kp + k;
    float t = -INFINITY;
    for (int i = 0; i < cnt; i++)
        t = fmaxf(t, base[(size_t)i * Kp] - cs[i]);

    out[b * Kp + k] = (cnt > 0) ? exp2f(t) : 0.f;
}

// ---------------- L2 normalize ----------------------------------------------
__device__ __forceinline__ float warpSum(float v) {
#pragma unroll
    for (int o = 16; o; o >>= 1) v += __shfl_xor_sync(0xffffffffu, v, o);
    return v;
}

__global__ __launch_bounds__(256)
void l2norm(float* __restrict__ out)
{
    const int b = blockIdx.x;
    float* o = out + b * Kp;
    const int tid = threadIdx.x;
    __shared__ float sh[8];
    __shared__ float bc;

    float s = 0.f;
    for (int i = tid; i < Kp; i += 256) { float v = o[i]; s = fmaf(v, v, s); }
    s = warpSum(s);
    if ((tid & 31) == 0) sh[tid >> 5] = s;
    __syncthreads();
    if (tid == 0) {
        float t = 0.f;
#pragma unroll
        for (int w = 0; w < 8; w++) t += sh[w];
        bc = 1.0f / fmaxf(sqrtf(t), 1e-12f);
    }
    __syncthreads();
    const float sc = bc;
    for (int i = tid; i < Kp; i += 256) o[i] *= sc;
}

// ---------------- launch (single stream) ------------------------------------
extern "C" void kernel_launch(void* const* d_in, const int* in_sizes, int n_in,
                              void* d_out, int out_size)
{
    const float* Q    = (const float*)d_in[0];
    const float* P    = (const float*)d_in[1];
    const float* temp = (const float*)d_in[2];
    const int*   mask = (const int*)d_in[3];
    float* out = (float*)d_out;

    cudaFuncSetAttribute(gemm_mma, cudaFuncAttributeMaxDynamicSharedMemorySize,
                         SMEM_GEMM);

    mask_scan<<<B_, Ls>>>(mask);
    scatter_idx<<<B_, Ls>>>(mask);               // fused offsets + scatter

    split_all<<<M_ + Kp, 192>>>(Q, P, temp);     // Q rows + P rows, vectorized

    dim3 gGemm(M_ / TILE_M, Kp / TILE_N);        // (128, 64); empty m-tiles exit
    gemm_mma<<<gGemm, 256, SMEM_GEMM>>>();

    row_stats<<<M_, 256>>>();
    dim3 gCol(Kp / 256, B_);
    col_max<<<gCol, 256>>>(out);
    l2norm<<<B_, 256>>>(out);
}